// round 12
// baseline (speedup 1.0000x reference)
#include <cuda_runtime.h>
#include <math.h>
#include <stdint.h>

#define SIZE 1000
#define NPTS 8
#define THREADS 256
#define CHUNK 2                        // 32B units per thread
#define BLK_U (THREADS * CHUNK)        // 512 units (16 KB) per block
#define MAXCAND 400

// ---------------------------------------------------------------------------
// tanh(100000*x) with exact fp32 saturation fast path:
// tanhf(t) rounds to exactly +/-1.0f for |t| >= ~9.02, i.e. |x| >= 1e-4.
// ---------------------------------------------------------------------------
__device__ __forceinline__ float vi_sgn(float x) {
    if (fabsf(x) >= 1e-4f) return copysignf(1.0f, x);
    return tanhf(100000.0f * x);
}

// Exact mask element (pre-transpose i=row, j=col), faithful to the reference.
__device__ __forceinline__ float vi_maskval(float a, float b, int i, int j) {
    float x1 = vi_sgn(a - (float)j);
    float y1 = vi_sgn(b - (float)(i + 1));
    float x3 = vi_sgn(a - (float)(j + 1));
    float y3 = vi_sgn(b - (float)i);
    float m1 = vi_sgn(y1 * x1);
    float m3 = vi_sgn(y3 * x3);
    return (1.0f - m1 * m3) * 0.5f;
}

// Transposed mask with zero padding: mt(p,q) = mask(i=q, j=p)
__device__ __forceinline__ float vi_mt(float a, float b, int p, int q) {
    if (p < 0 || p >= SIZE || q < 0 || q >= SIZE) return 0.0f;
    return vi_maskval(a, b, q, p);
}

// ---------------------------------------------------------------------------
// Fused fill, barrier-free fast path (R10 geometry: 2442 x 256), with 256-bit
// stores: each thread writes 2 x ulonglong4 (32B) block-interleaved -> on
// sm_103a nvcc emits STG.256, halving LSU store-issue count vs STG.128.
//   - stores issued first, no dependencies
//   - every warp's lanes 0..7 compute the closed-form candidate offsets
//     (single 1.0 at (jc*1000+ic)*10+cls per interior, saturated point)
//   - ballot: candidate in this block's 16KB span? almost always no ->
//     warp done. If yes, the thread that zero-stored that 32B unit applies
//     atomicMax (same-thread same-address ordering, no barrier).
//   - non-saturated inputs (near-integer band): block-uniform slow path
//     with exact 7x7 evaluation, shared list and __syncthreads.
// ---------------------------------------------------------------------------
__global__ void __launch_bounds__(THREADS) vi_fused_kernel(
        const float* __restrict__ z_pos,
        const int* __restrict__ z_cls,
        ulonglong4* __restrict__ out8, int n8) {
    __shared__ int   s_off[MAXCAND];
    __shared__ float s_val[MAXCAND];
    __shared__ int   s_cnt;

    int tid  = threadIdx.x;
    int lane = tid & 31;

    // early predicated input loads (every warp; broadcast addresses)
    float a = 0.f, b = 0.f;
    int   c = 0;
    if (lane < NPTS) {
        float2 zp = ((const float2*)z_pos)[lane];
        a = zp.x * 1000.0f;
        b = zp.y * 1000.0f;
        c = z_cls[lane];
    }

    // 1. zero stores first — the bandwidth-bound bulk, no dependencies
    ulonglong4 z;
    z.x = 0ull; z.y = 0ull; z.z = 0ull; z.w = 0ull;
    int blk_u = blockIdx.x * BLK_U;
    {
        int i = blk_u + tid;
        #pragma unroll
        for (int u = 0; u < CHUNK; u++) {
            if (i < n8) out8[i] = z;
            i += THREADS;
        }
    }

    // 2. closed-form candidate per lane (overlaps store drain)
    int  off = -1;
    bool sat = true;
    if (lane < NPTS) {
        int  jc = (int)floorf(a);
        int  ic = (int)floorf(b);
        float fa = a - (float)jc;
        float fb = b - (float)ic;
        sat = (fa >= 1e-4f) && (fa <= 1.0f - 1e-4f) &&
              (fb >= 1e-4f) && (fb <= 1.0f - 1e-4f);
        if (sat && jc >= 1 && jc <= SIZE - 2 && ic >= 1 && ic <= SIZE - 2)
            off = (jc * SIZE + ic) * 10 + c;
    }

    unsigned bad = __ballot_sync(0xffffffffu, (lane < NPTS) && !sat);

    if (bad == 0) {
        // 3. fast path: block-uniform, barrier-free
        int r = off >> 3;                           // 32B unit of candidate
        bool inblk = (off >= 0) && (r >= blk_u) && (r < blk_u + BLK_U);
        unsigned m = __ballot_sync(0xffffffffu, inblk);
        while (m) {
            int n = __ffs(m) - 1;
            m &= m - 1;
            int o  = __shfl_sync(0xffffffffu, off, n);
            int ru = (o >> 3) - blk_u;              // unit index within block
            if ((ru & (THREADS - 1)) == tid) {      // I zero-stored this unit
                atomicMax((int*)((float*)out8 + o), __float_as_int(1.0f));
            }
        }
    } else {
        // 4. slow path (rare near-integer band): exact 7x7, shared list
        if (tid == 0) s_cnt = 0;
        __syncthreads();
        if (tid < NPTS) {
            int jc = (int)floorf(a);
            int ic = (int)floorf(b);
            for (int t = 0; t < 49; t++) {
                int p = jc + (t % 7) - 3;
                int q = ic + (t / 7) - 3;
                if (p < 0 || p >= SIZE || q < 0 || q >= SIZE) continue;
                float conv = vi_mt(a, b, p - 1, q) + vi_mt(a, b, p + 1, q) +
                             vi_mt(a, b, p, q - 1) + vi_mt(a, b, p, q + 1);
                float v = conv - 3.0f;
                if (v > 0.0f) {
                    int k = atomicAdd(&s_cnt, 1);
                    s_off[k] = (p * SIZE + q) * 10 + c;
                    s_val[k] = v;
                }
            }
        }
        __syncthreads();   // also makes all block zero-stores visible
        int cnt = s_cnt;
        for (int k = tid; k < cnt; k += THREADS) {
            int r = s_off[k] >> 3;
            if (r >= blk_u && r < blk_u + BLK_U)
                atomicMax((int*)((float*)out8 + s_off[k]),
                          __float_as_int(s_val[k]));
        }
    }
}

extern "C" void kernel_launch(void* const* d_in, const int* in_sizes, int n_in,
                              void* d_out, int out_size) {
    const float* z_pos = (const float*)d_in[0];  // [8,2] fp32
    const int*   z_cls = (const int*)d_in[1];    // [8] int32
    float* out = (float*)d_out;                  // [1000,1000,10] fp32

    int n8 = out_size / 8;                       // 1,250,000 32B units
    int blocks = (n8 + BLK_U - 1) / BLK_U;       // 2442
    vi_fused_kernel<<<blocks, THREADS>>>(z_pos, z_cls, (ulonglong4*)out, n8);
}

// round 13
// speedup vs baseline: 1.0151x; 1.0151x over previous
#include <cuda_runtime.h>
#include <math.h>
#include <stdint.h>

#define SIZE 1000
#define NPTS 8
#define THREADS 256
#define CHUNK 4                       // float4 stores per thread
#define BLK_F4 (THREADS * CHUNK)      // 1024 float4s (16 KB) per block
#define MAXCAND 400

// ---------------------------------------------------------------------------
// tanh(100000*x) with exact fp32 saturation fast path:
// tanhf(t) rounds to exactly +/-1.0f for |t| >= ~9.02, i.e. |x| >= 1e-4.
// ---------------------------------------------------------------------------
__device__ __forceinline__ float vi_sgn(float x) {
    if (fabsf(x) >= 1e-4f) return copysignf(1.0f, x);
    return tanhf(100000.0f * x);
}

// Exact mask element (pre-transpose i=row, j=col), faithful to the reference.
__device__ __forceinline__ float vi_maskval(float a, float b, int i, int j) {
    float x1 = vi_sgn(a - (float)j);
    float y1 = vi_sgn(b - (float)(i + 1));
    float x3 = vi_sgn(a - (float)(j + 1));
    float y3 = vi_sgn(b - (float)i);
    float m1 = vi_sgn(y1 * x1);
    float m3 = vi_sgn(y3 * x3);
    return (1.0f - m1 * m3) * 0.5f;
}

// Transposed mask with zero padding: mt(p,q) = mask(i=q, j=p)
__device__ __forceinline__ float vi_mt(float a, float b, int p, int q) {
    if (p < 0 || p >= SIZE || q < 0 || q >= SIZE) return 0.0f;
    return vi_maskval(a, b, q, p);
}

// ---------------------------------------------------------------------------
// Fused fill, barrier-free fast path (proven optimum: 2442 x 256 x STG.128):
//   - 4 block-interleaved float4 zero stores per thread, issued first
//   - every warp's lanes 0..7 compute the 8 closed-form candidate offsets
//     (single 1.0 at (jc*1000+ic)*10+cls per interior, saturated point)
//   - ballot: candidate in this block's 16KB span? almost always no ->
//     warp done. If yes, the thread that zero-stored that float4 applies
//     atomicMax (same-thread same-address ordering, no barrier).
//   - non-saturated inputs (near-integer band): block-uniform slow path
//     with exact 7x7 evaluation, shared list and __syncthreads.
// ---------------------------------------------------------------------------
__global__ void __launch_bounds__(THREADS) vi_fused_kernel(
        const float* __restrict__ z_pos,
        const int* __restrict__ z_cls,
        float4* __restrict__ out4, int n4) {
    __shared__ int   s_off[MAXCAND];
    __shared__ float s_val[MAXCAND];
    __shared__ int   s_cnt;

    int tid  = threadIdx.x;
    int lane = tid & 31;

    // early predicated input loads (every warp; broadcast addresses, L2-hit)
    float a = 0.f, b = 0.f;
    int   c = 0;
    if (lane < NPTS) {
        float2 zp = ((const float2*)z_pos)[lane];
        c = z_cls[lane];
        a = zp.x * 1000.0f;
        b = zp.y * 1000.0f;
    }

    // 1. zero stores first — the bandwidth-bound bulk, no dependencies
    const float4 z = make_float4(0.f, 0.f, 0.f, 0.f);
    int blk_f4 = blockIdx.x * BLK_F4;
    {
        int i = blk_f4 + tid;
        #pragma unroll
        for (int u = 0; u < CHUNK; u++) {
            if (i < n4) out4[i] = z;
            i += THREADS;
        }
    }

    // 2. closed-form candidate per lane (overlaps store drain)
    int  off = -1;
    bool sat = true;
    if (lane < NPTS) {
        int  jc = (int)floorf(a);
        int  ic = (int)floorf(b);
        float fa = a - (float)jc;
        float fb = b - (float)ic;
        sat = (fa >= 1e-4f) && (fa <= 1.0f - 1e-4f) &&
              (fb >= 1e-4f) && (fb <= 1.0f - 1e-4f);
        if (sat && jc >= 1 && jc <= SIZE - 2 && ic >= 1 && ic <= SIZE - 2)
            off = (jc * SIZE + ic) * 10 + c;
    }

    unsigned bad = __ballot_sync(0xffffffffu, (lane < NPTS) && !sat);

    if (bad == 0) {
        // 3. fast path: block-uniform, barrier-free
        int blk_lo = blk_f4 * 4;                  // first element of block
        bool inblk = (off >= blk_lo) && (off < blk_lo + BLK_F4 * 4);
        unsigned m = __ballot_sync(0xffffffffu, inblk);
        while (m) {
            int n = __ffs(m) - 1;
            m &= m - 1;
            int o = __shfl_sync(0xffffffffu, off, n);
            int r = (o >> 2) - blk_f4;            // float4 index within block
            if ((r & (THREADS - 1)) == tid) {     // I zero-stored this float4
                atomicMax((int*)((float*)out4 + o), __float_as_int(1.0f));
            }
        }
    } else {
        // 4. slow path (rare near-integer band): exact 7x7, shared list
        if (tid == 0) s_cnt = 0;
        __syncthreads();
        if (tid < NPTS) {
            int jc = (int)floorf(a);
            int ic = (int)floorf(b);
            for (int t = 0; t < 49; t++) {
                int p = jc + (t % 7) - 3;
                int q = ic + (t / 7) - 3;
                if (p < 0 || p >= SIZE || q < 0 || q >= SIZE) continue;
                float conv = vi_mt(a, b, p - 1, q) + vi_mt(a, b, p + 1, q) +
                             vi_mt(a, b, p, q - 1) + vi_mt(a, b, p, q + 1);
                float v = conv - 3.0f;
                if (v > 0.0f) {
                    int k = atomicAdd(&s_cnt, 1);
                    s_off[k] = (p * SIZE + q) * 10 + c;
                    s_val[k] = v;
                }
            }
        }
        __syncthreads();   // also makes all block zero-stores visible
        int cnt = s_cnt;
        int e_lo = blk_f4 * 4;
        for (int k = tid; k < cnt; k += THREADS) {
            unsigned d = (unsigned)(s_off[k] - e_lo);
            if (d < (unsigned)(BLK_F4 * 4))
                atomicMax((int*)((float*)out4 + s_off[k]),
                          __float_as_int(s_val[k]));
        }
    }
}

extern "C" void kernel_launch(void* const* d_in, const int* in_sizes, int n_in,
                              void* d_out, int out_size) {
    const float* z_pos = (const float*)d_in[0];  // [8,2] fp32
    const int*   z_cls = (const int*)d_in[1];    // [8] int32
    float* out = (float*)d_out;                  // [1000,1000,10] fp32

    int n4 = out_size / 4;                       // 2,500,000 float4s
    int blocks = (n4 + BLK_F4 - 1) / BLK_F4;     // 2442
    vi_fused_kernel<<<blocks, THREADS>>>(z_pos, z_cls, (float4*)out, n4);
}

// round 14
// speedup vs baseline: 1.1805x; 1.1629x over previous
#include <cuda_runtime.h>
#include <math.h>
#include <stdint.h>

#define SIZE 1000
#define NPTS 8

// ---------------------------------------------------------------------------
// tanh(100000*x) with exact fp32 saturation fast path:
// tanhf(t) rounds to exactly +/-1.0f for |t| >= ~9.02, i.e. |x| >= 1e-4.
// ---------------------------------------------------------------------------
__device__ __forceinline__ float vi_sgn(float x) {
    if (fabsf(x) >= 1e-4f) return copysignf(1.0f, x);
    return tanhf(100000.0f * x);
}

// Exact mask element (pre-transpose i=row, j=col), faithful to the reference.
__device__ __forceinline__ float vi_maskval(float a, float b, int i, int j) {
    float x1 = vi_sgn(a - (float)j);
    float y1 = vi_sgn(b - (float)(i + 1));
    float x3 = vi_sgn(a - (float)(j + 1));
    float y3 = vi_sgn(b - (float)i);
    float m1 = vi_sgn(y1 * x1);
    float m3 = vi_sgn(y3 * x3);
    return (1.0f - m1 * m3) * 0.5f;
}

// Transposed mask with zero padding: mt(p,q) = mask(i=q, j=p)
__device__ __forceinline__ float vi_mt(float a, float b, int p, int q) {
    if (p < 0 || p >= SIZE || q < 0 || q >= SIZE) return 0.0f;
    return vi_maskval(a, b, q, p);
}

// ---------------------------------------------------------------------------
// Tiny fix-up kernel, runs after cudaMemsetAsync(out, 0) on the same stream.
// One warp: lanes 0..7 own one input point each.
//   - closed form (both fractional parts saturated): the whole output for
//     this point is a single 1.0 at out[(jc*1000+ic)*10 + cls] (interior).
//   - near-integer band (rare): exact 7x7 window evaluation with the true
//     tanhf chain, identical math to the reference.
// atomicMax on int bits is exact for non-negative floats; multiple points
// may collide on the same cell/class.
// ---------------------------------------------------------------------------
__global__ void vi_point_kernel(const float* __restrict__ z_pos,
                                const int* __restrict__ z_cls,
                                float* __restrict__ out) {
    int lane = threadIdx.x;
    if (lane >= NPTS) return;

    float2 zp = ((const float2*)z_pos)[lane];
    float a = zp.x * 1000.0f;
    float b = zp.y * 1000.0f;
    int   c = z_cls[lane];

    int  jc = (int)floorf(a);
    int  ic = (int)floorf(b);
    float fa = a - (float)jc;
    float fb = b - (float)ic;
    bool sat = (fa >= 1e-4f) && (fa <= 1.0f - 1e-4f) &&
               (fb >= 1e-4f) && (fb <= 1.0f - 1e-4f);

    if (sat) {
        if (jc >= 1 && jc <= SIZE - 2 && ic >= 1 && ic <= SIZE - 2) {
            atomicMax((int*)&out[(jc * SIZE + ic) * 10 + c],
                      __float_as_int(1.0f));
        }
    } else {
        // rare near-integer band: exact 7x7 window evaluation
        for (int t = 0; t < 49; t++) {
            int p = jc + (t % 7) - 3;
            int q = ic + (t / 7) - 3;
            if (p < 0 || p >= SIZE || q < 0 || q >= SIZE) continue;
            float conv = vi_mt(a, b, p - 1, q) + vi_mt(a, b, p + 1, q) +
                         vi_mt(a, b, p, q - 1) + vi_mt(a, b, p, q + 1);
            float v = conv - 3.0f;
            if (v > 0.0f)
                atomicMax((int*)&out[(p * SIZE + q) * 10 + c],
                          __float_as_int(v));
        }
    }
}

extern "C" void kernel_launch(void* const* d_in, const int* in_sizes, int n_in,
                              void* d_out, int out_size) {
    const float* z_pos = (const float*)d_in[0];  // [8,2] fp32
    const int*   z_cls = (const int*)d_in[1];    // [8] int32
    float* out = (float*)d_out;                  // [1000,1000,10] fp32
    (void)in_sizes; (void)n_in;

    // Driver-optimized fill, captured as a graph memset node.
    cudaMemsetAsync(out, 0, (size_t)out_size * sizeof(float), 0);
    // Stream-ordered fix-up: <=8 scattered atomicMax writes.
    vi_point_kernel<<<1, 32>>>(z_pos, z_cls, out);
}

// round 15
// speedup vs baseline: 1.3732x; 1.1633x over previous
#include <cuda_runtime.h>
#include <math.h>
#include <stdint.h>

#define SIZE 1000
#define NPTS 8
#define THREADS 256
#define CHUNK 4                       // float4 stores per thread
#define BLK_F4 (THREADS * CHUNK)      // 1024 float4s (16 KB) per block
#define N4 2500000                    // total float4s (10M floats / 4)
#define MAXCAND 400

// ---------------------------------------------------------------------------
// tanh(100000*x) with exact fp32 saturation fast path:
// tanhf(t) rounds to exactly +/-1.0f for |t| >= ~9.02, i.e. |x| >= 1e-4.
// ---------------------------------------------------------------------------
__device__ __forceinline__ float vi_sgn(float x) {
    if (fabsf(x) >= 1e-4f) return copysignf(1.0f, x);
    return tanhf(100000.0f * x);
}

// Exact mask element (pre-transpose i=row, j=col), faithful to the reference.
__device__ __forceinline__ float vi_maskval(float a, float b, int i, int j) {
    float x1 = vi_sgn(a - (float)j);
    float y1 = vi_sgn(b - (float)(i + 1));
    float x3 = vi_sgn(a - (float)(j + 1));
    float y3 = vi_sgn(b - (float)i);
    float m1 = vi_sgn(y1 * x1);
    float m3 = vi_sgn(y3 * x3);
    return (1.0f - m1 * m3) * 0.5f;
}

// Transposed mask with zero padding: mt(p,q) = mask(i=q, j=p)
__device__ __forceinline__ float vi_mt(float a, float b, int p, int q) {
    if (p < 0 || p >= SIZE || q < 0 || q >= SIZE) return 0.0f;
    return vi_maskval(a, b, q, p);
}

// ---------------------------------------------------------------------------
// Fused fill, barrier-free fast path (champion config: 2442 x 256, STG.128).
//   - 4 block-interleaved float4 zero stores per thread, issued first,
//     unpredicated: the last block wraps its out-of-range indices back onto
//     its own span (extra zero stores). Safe: fast-path candidates have
//     offset <= 9,989,989 < 9,996,288 (last block's base), and the slow
//     path orders all block stores with __syncthreads before fix-up.
//   - every warp's lanes 0..7 compute the 8 closed-form candidate offsets
//     (single 1.0 at (jc*1000+ic)*10+cls per interior, saturated point)
//   - ballot: candidate in this block's 16KB span? almost always no ->
//     warp done. If yes, the thread that zero-stored that float4 applies
//     atomicMax (same-thread same-address ordering, no barrier).
//   - non-saturated inputs (near-integer band): block-uniform slow path
//     with exact 7x7 evaluation, shared list and __syncthreads.
// ---------------------------------------------------------------------------
__global__ void __launch_bounds__(THREADS) vi_fused_kernel(
        const float* __restrict__ z_pos,
        const int* __restrict__ z_cls,
        float4* __restrict__ out4) {
    __shared__ int   s_off[MAXCAND];
    __shared__ float s_val[MAXCAND];
    __shared__ int   s_cnt;

    int tid  = threadIdx.x;
    int lane = tid & 31;

    // early predicated input loads (every warp; broadcast addresses, L2-hit)
    float a = 0.f, b = 0.f;
    int   c = 0;
    if (lane < NPTS) {
        float2 zp = ((const float2*)z_pos)[lane];
        a = zp.x * 1000.0f;
        b = zp.y * 1000.0f;
        c = z_cls[lane];
    }

    // 1. zero stores first — the bandwidth-bound bulk, no dependencies
    const float4 z = make_float4(0.f, 0.f, 0.f, 0.f);
    int blk_f4 = blockIdx.x * BLK_F4;
    {
        int i = blk_f4 + tid;
        #pragma unroll
        for (int u = 0; u < CHUNK; u++) {
            out4[min(i, N4 - 1)] = z;      // wrap-in-range for the tail block
            i += THREADS;
        }
    }

    // 2. closed-form candidate per lane (overlaps store drain)
    int  off = -1;
    bool sat = true;
    if (lane < NPTS) {
        int  jc = (int)floorf(a);
        int  ic = (int)floorf(b);
        float fa = a - (float)jc;
        float fb = b - (float)ic;
        sat = (fa >= 1e-4f) && (fa <= 1.0f - 1e-4f) &&
              (fb >= 1e-4f) && (fb <= 1.0f - 1e-4f);
        if (sat && jc >= 1 && jc <= SIZE - 2 && ic >= 1 && ic <= SIZE - 2)
            off = (jc * SIZE + ic) * 10 + c;
    }

    unsigned bad = __ballot_sync(0xffffffffu, (lane < NPTS) && !sat);

    if (bad == 0) {
        // 3. fast path: block-uniform, barrier-free
        int blk_lo = blk_f4 * 4;                  // first element of block
        bool inblk = (off >= blk_lo) && (off < blk_lo + BLK_F4 * 4);
        unsigned m = __ballot_sync(0xffffffffu, inblk);
        while (m) {
            int n = __ffs(m) - 1;
            m &= m - 1;
            int o = __shfl_sync(0xffffffffu, off, n);
            int r = (o >> 2) - blk_f4;            // float4 index within block
            if ((r & (THREADS - 1)) == tid) {     // I zero-stored this float4
                atomicMax((int*)((float*)out4 + o), __float_as_int(1.0f));
            }
        }
    } else {
        // 4. slow path (rare near-integer band): exact 7x7, shared list
        if (tid == 0) s_cnt = 0;
        __syncthreads();
        if (tid < NPTS) {
            int jc = (int)floorf(a);
            int ic = (int)floorf(b);
            for (int t = 0; t < 49; t++) {
                int p = jc + (t % 7) - 3;
                int q = ic + (t / 7) - 3;
                if (p < 0 || p >= SIZE || q < 0 || q >= SIZE) continue;
                float conv = vi_mt(a, b, p - 1, q) + vi_mt(a, b, p + 1, q) +
                             vi_mt(a, b, p, q - 1) + vi_mt(a, b, p, q + 1);
                float v = conv - 3.0f;
                if (v > 0.0f) {
                    int k = atomicAdd(&s_cnt, 1);
                    s_off[k] = (p * SIZE + q) * 10 + c;
                    s_val[k] = v;
                }
            }
        }
        __syncthreads();   // also makes all block zero-stores visible
        int cnt = s_cnt;
        int e_lo = blk_f4 * 4;
        for (int k = tid; k < cnt; k += THREADS) {
            unsigned d = (unsigned)(s_off[k] - e_lo);
            if (d < (unsigned)(BLK_F4 * 4))
                atomicMax((int*)((float*)out4 + s_off[k]),
                          __float_as_int(s_val[k]));
        }
    }
}

extern "C" void kernel_launch(void* const* d_in, const int* in_sizes, int n_in,
                              void* d_out, int out_size) {
    const float* z_pos = (const float*)d_in[0];  // [8,2] fp32
    const int*   z_cls = (const int*)d_in[1];    // [8] int32
    float* out = (float*)d_out;                  // [1000,1000,10] fp32
    (void)in_sizes; (void)n_in; (void)out_size;

    int blocks = (N4 + BLK_F4 - 1) / BLK_F4;     // 2442
    vi_fused_kernel<<<blocks, THREADS>>>(z_pos, z_cls, (float4*)out);
}

// round 16
// speedup vs baseline: 1.4060x; 1.0239x over previous
#include <cuda_runtime.h>
#include <math.h>
#include <stdint.h>

#define SIZE 1000
#define NPTS 8
#define THREADS 256
#define CHUNK 2                       // float4 stores per thread
#define BLK_F4 (THREADS * CHUNK)      // 512 float4s (8 KB) per block
#define N4 2500000                    // total float4s (10M floats / 4)
#define MAXCAND 400

// ---------------------------------------------------------------------------
// tanh(100000*x) with exact fp32 saturation fast path:
// tanhf(t) rounds to exactly +/-1.0f for |t| >= ~9.02, i.e. |x| >= 1e-4.
// ---------------------------------------------------------------------------
__device__ __forceinline__ float vi_sgn(float x) {
    if (fabsf(x) >= 1e-4f) return copysignf(1.0f, x);
    return tanhf(100000.0f * x);
}

// Exact mask element (pre-transpose i=row, j=col), faithful to the reference.
__device__ __forceinline__ float vi_maskval(float a, float b, int i, int j) {
    float x1 = vi_sgn(a - (float)j);
    float y1 = vi_sgn(b - (float)(i + 1));
    float x3 = vi_sgn(a - (float)(j + 1));
    float y3 = vi_sgn(b - (float)i);
    float m1 = vi_sgn(y1 * x1);
    float m3 = vi_sgn(y3 * x3);
    return (1.0f - m1 * m3) * 0.5f;
}

// Transposed mask with zero padding: mt(p,q) = mask(i=q, j=p)
__device__ __forceinline__ float vi_mt(float a, float b, int p, int q) {
    if (p < 0 || p >= SIZE || q < 0 || q >= SIZE) return 0.0f;
    return vi_maskval(a, b, q, p);
}

// ---------------------------------------------------------------------------
// Fused fill, barrier-free fast path. Geometry probe: 4884 x 256 x CHUNK 2
// (8 KB per block; thinner than the 2442 x 16 KB champion).
//   - 2 block-interleaved float4 zero stores per thread, issued first,
//     unpredicated: the tail block wraps out-of-range indices onto its own
//     span (extra zero stores; candidates provably below the tail span on
//     the fast path, slow path is barrier-ordered).
//   - every warp's lanes 0..7 compute the 8 closed-form candidate offsets
//     (single 1.0 at (jc*1000+ic)*10+cls per interior, saturated point)
//   - ballot: candidate in this block's span? almost always no -> done.
//     If yes, the thread that zero-stored that float4 applies atomicMax
//     (same-thread same-address ordering, no barrier needed).
//   - non-saturated inputs (near-integer band): block-uniform slow path
//     with exact 7x7 evaluation, shared list and __syncthreads.
// ---------------------------------------------------------------------------
__global__ void __launch_bounds__(THREADS) vi_fused_kernel(
        const float* __restrict__ z_pos,
        const int* __restrict__ z_cls,
        float4* __restrict__ out4) {
    __shared__ int   s_off[MAXCAND];
    __shared__ float s_val[MAXCAND];
    __shared__ int   s_cnt;

    int tid  = threadIdx.x;
    int lane = tid & 31;

    // early predicated input loads (every warp; broadcast addresses, L2-hit)
    float a = 0.f, b = 0.f;
    int   c = 0;
    if (lane < NPTS) {
        float2 zp = ((const float2*)z_pos)[lane];
        a = zp.x * 1000.0f;
        b = zp.y * 1000.0f;
        c = z_cls[lane];
    }

    // 1. zero stores first — the bandwidth-bound bulk, no dependencies
    const float4 z = make_float4(0.f, 0.f, 0.f, 0.f);
    int blk_f4 = blockIdx.x * BLK_F4;
    {
        int i = blk_f4 + tid;
        #pragma unroll
        for (int u = 0; u < CHUNK; u++) {
            out4[min(i, N4 - 1)] = z;      // wrap-in-range for the tail block
            i += THREADS;
        }
    }

    // 2. closed-form candidate per lane (overlaps store drain)
    int  off = -1;
    bool sat = true;
    if (lane < NPTS) {
        int  jc = (int)floorf(a);
        int  ic = (int)floorf(b);
        float fa = a - (float)jc;
        float fb = b - (float)ic;
        sat = (fa >= 1e-4f) && (fa <= 1.0f - 1e-4f) &&
              (fb >= 1e-4f) && (fb <= 1.0f - 1e-4f);
        if (sat && jc >= 1 && jc <= SIZE - 2 && ic >= 1 && ic <= SIZE - 2)
            off = (jc * SIZE + ic) * 10 + c;
    }

    unsigned bad = __ballot_sync(0xffffffffu, (lane < NPTS) && !sat);

    if (bad == 0) {
        // 3. fast path: block-uniform, barrier-free
        int blk_lo = blk_f4 * 4;                  // first element of block
        bool inblk = (off >= blk_lo) && (off < blk_lo + BLK_F4 * 4);
        unsigned m = __ballot_sync(0xffffffffu, inblk);
        while (m) {
            int n = __ffs(m) - 1;
            m &= m - 1;
            int o = __shfl_sync(0xffffffffu, off, n);
            int r = (o >> 2) - blk_f4;            // float4 index within block
            if ((r & (THREADS - 1)) == tid) {     // I zero-stored this float4
                atomicMax((int*)((float*)out4 + o), __float_as_int(1.0f));
            }
        }
    } else {
        // 4. slow path (rare near-integer band): exact 7x7, shared list
        if (tid == 0) s_cnt = 0;
        __syncthreads();
        if (tid < NPTS) {
            int jc = (int)floorf(a);
            int ic = (int)floorf(b);
            for (int t = 0; t < 49; t++) {
                int p = jc + (t % 7) - 3;
                int q = ic + (t / 7) - 3;
                if (p < 0 || p >= SIZE || q < 0 || q >= SIZE) continue;
                float conv = vi_mt(a, b, p - 1, q) + vi_mt(a, b, p + 1, q) +
                             vi_mt(a, b, p, q - 1) + vi_mt(a, b, p, q + 1);
                float v = conv - 3.0f;
                if (v > 0.0f) {
                    int k = atomicAdd(&s_cnt, 1);
                    s_off[k] = (p * SIZE + q) * 10 + c;
                    s_val[k] = v;
                }
            }
        }
        __syncthreads();   // also makes all block zero-stores visible
        int cnt = s_cnt;
        int e_lo = blk_f4 * 4;
        for (int k = tid; k < cnt; k += THREADS) {
            unsigned d = (unsigned)(s_off[k] - e_lo);
            if (d < (unsigned)(BLK_F4 * 4))
                atomicMax((int*)((float*)out4 + s_off[k]),
                          __float_as_int(s_val[k]));
        }
    }
}

extern "C" void kernel_launch(void* const* d_in, const int* in_sizes, int n_in,
                              void* d_out, int out_size) {
    const float* z_pos = (const float*)d_in[0];  // [8,2] fp32
    const int*   z_cls = (const int*)d_in[1];    // [8] int32
    float* out = (float*)d_out;                  // [1000,1000,10] fp32
    (void)in_sizes; (void)n_in; (void)out_size;

    int blocks = (N4 + BLK_F4 - 1) / BLK_F4;     // 4883
    vi_fused_kernel<<<blocks, THREADS>>>(z_pos, z_cls, (float4*)out);
}